// round 7
// baseline (speedup 1.0000x reference)
#include <cuda_runtime.h>
#include <cuda_bf16.h>

#define KMAX 8
#define NT 256
#define NWARP (NT / 32)
#define FULLM 0xffffffffu

// out[b,d] = (1/k) * sum_j (1/c_j) * sum_{t: seqs[b,t]==aval_j, t<L, t+j+1<L} emb[b, t+j+1, d]
//   L      = nonzero prefix length of seqs[b,:] (right-padded, valid ids >= 1)
//   aval_j = seqs[b, max(L-1-j, 0)]
//   c_j    = # of t in [0,L) with seqs[b,t]==aval_j
__global__ __launch_bounds__(NT)
void wave_kernel(const int* __restrict__ seqs,
                 const float* __restrict__ emb,
                 const int* __restrict__ kptr,
                 float* __restrict__ out,
                 int S, int D) {
    const int b    = blockIdx.x;
    const int tid  = threadIdx.x;
    const int lane = tid & 31;
    const int warp = tid >> 5;

    extern __shared__ int smem[];
    float* acc  = (float*)smem;                // KMAX*D floats
    int*   sseq = smem + KMAX * 64 * ((D + 63) / 64);  // only used on general path

    __shared__ int warpMin[NWARP];
    __shared__ int cnt[KMAX];

    const int* seq = seqs + (size_t)b * S;
    int k = *kptr;
    if (k > KMAX) k = KMAX;
    if (k < 1) k = 1;

    if (tid < KMAX) cnt[tid] = 0;
    for (int i = tid; i < KMAX * D; i += NT) acc[i] = 0.0f;

    const float* eb = emb + (size_t)b * S * D;
    const bool deven = (D & 1) == 0;
    const float invk = 1.0f / (float)k;

    if (S == (NT << 3)) {
        // ================= FAST PATH: exactly 8 ints per thread =================
        const int base = tid << 3;
        int4 a0 = ((const int4*)(seq + base))[0];
        int4 a1 = ((const int4*)(seq + base))[1];
        int vv[8];
        vv[0]=a0.x; vv[1]=a0.y; vv[2]=a0.z; vv[3]=a0.w;
        vv[4]=a1.x; vv[5]=a1.y; vv[6]=a1.z; vv[7]=a1.w;

        // next chunk's first element: next lane's vv[0]; lane 31 loads (L1-hot)
        int nxt = __shfl_down_sync(FULLM, vv[0], 1);
        if (lane == 31) nxt = (base + 8 < S) ? __ldg(seq + base + 8) : 0;

        int cand = S;
        if (base == 0 && vv[0] == 0) cand = 0;
        #pragma unroll
        for (int i = 0; i < 7; i++)
            if (vv[i] != 0 && vv[i + 1] == 0) cand = base + i + 1;
        if (vv[7] != 0 && nxt == 0) cand = base + 8;

        #pragma unroll
        for (int o = 16; o; o >>= 1) {
            int other = __shfl_down_sync(FULLM, cand, o);
            cand = other < cand ? other : cand;
        }
        if (lane == 0) warpMin[warp] = cand;
        __syncthreads();                                   // BARRIER 1

        int L = warpMin[0];
        #pragma unroll
        for (int w = 1; w < NWARP; w++) { int m = warpMin[w]; L = m < L ? m : L; }

        // per-warp redundant anchor fetch (L1/L2-hot), broadcast via shfl
        int my_aval = 0;
        if (lane < k) {
            int a = L - 1 - lane;
            my_aval = __ldg(seq + (a > 0 ? a : 0));
        }

        for (int j = 0; j < k; j++) {
            const int av = __shfl_sync(FULLM, my_aval, j);
            unsigned mymask = 0;
            #pragma unroll
            for (int i = 0; i < 8; i++)
                if (vv[i] == av && vv[i] != 0) mymask |= (1u << i);

            int wcnt = __reduce_add_sync(FULLM, __popc(mymask));
            unsigned tmask = __ballot_sync(FULLM, mymask != 0);
            if (!tmask) continue;
            if (lane == 0) atomicAdd(&cnt[j], wcnt);

            // warp-cooperative gather of each matched row (rare)
            float* aj = acc + j * D;
            while (tmask) {
                const int src = __ffs(tmask) - 1;
                tmask &= tmask - 1;
                unsigned em = __shfl_sync(FULLM, mymask, src);
                const int sbase = (((warp << 5) + src) << 3) + j + 1;
                while (em) {
                    const int i = __ffs(em) - 1;
                    em &= em - 1;
                    const int s = sbase + i;
                    if (s < L) {
                        const float* row = eb + (size_t)s * D;
                        if (deven) {
                            for (int d = 2 * lane; d < D; d += 64) {
                                float2 e2 = *(const float2*)(row + d);
                                atomicAdd(&aj[d],     e2.x);
                                atomicAdd(&aj[d + 1], e2.y);
                            }
                        } else {
                            for (int d = lane; d < D; d += 32)
                                atomicAdd(&aj[d], row[d]);
                        }
                    }
                }
            }
        }
        __syncthreads();                                   // BARRIER 2
    } else {
        // ================= GENERAL PATH (any S) =================
        __shared__ int sLsh;
        if (tid == 0) sLsh = S;
        for (int i = tid; i < S; i += NT) sseq[i] = seq[i];
        __syncthreads();
        for (int i = tid; i < S; i += NT) {
            int v = sseq[i];
            if (i == 0 && v == 0) atomicMin(&sLsh, 0);
            if (v != 0 && (i + 1 == S || sseq[i + 1] == 0)) atomicMin(&sLsh, i + 1);
        }
        __syncthreads();
        const int L = sLsh;
        int my_aval = 0;
        if (lane < k) {
            int a = L - 1 - lane;
            my_aval = sseq[a > 0 ? a : 0];
        }
        for (int t0 = warp * 32; t0 < L; t0 += NT) {
            const int t = t0 + lane;
            const int v = (t < L) ? sseq[t] : 0;
            for (int j = 0; j < k; j++) {
                const int av = __shfl_sync(FULLM, my_aval, j);
                unsigned m = __ballot_sync(FULLM, v == av && v != 0);
                if (!m) continue;
                if (lane == 0) atomicAdd(&cnt[j], __popc(m));
                float* aj = acc + j * D;
                while (m) {
                    const int l = __ffs(m) - 1;
                    m &= m - 1;
                    const int s = t0 + l + j + 1;
                    if (s < L) {
                        const float* row = eb + (size_t)s * D;
                        if (deven) {
                            for (int d = 2 * lane; d < D; d += 64) {
                                float2 e2 = *(const float2*)(row + d);
                                atomicAdd(&aj[d],     e2.x);
                                atomicAdd(&aj[d + 1], e2.y);
                            }
                        } else {
                            for (int d = lane; d < D; d += 32)
                                atomicAdd(&aj[d], row[d]);
                        }
                    }
                }
            }
        }
        __syncthreads();
    }

    // ---- epilogue ----
    for (int d = tid; d < D; d += NT) {
        float s = 0.0f;
        for (int j = 0; j < k; j++) {
            int c = cnt[j];
            if (c > 0) s += acc[j * D + d] / (float)c;
        }
        out[(size_t)b * D + d] = s * invk;
    }
}

extern "C" void kernel_launch(void* const* d_in, const int* in_sizes, int n_in,
                              void* d_out, int out_size) {
    const int*   seqs = (const int*)d_in[0];
    const float* emb  = (const float*)d_in[1];
    const int*   kptr = (const int*)d_in[2];
    float*       out  = (float*)d_out;

    const int n_seq = in_sizes[0];   // B*S
    const int n_emb = in_sizes[1];   // B*S*D
    const int D = n_emb / n_seq;
    const int B = out_size / D;
    const int S = n_seq / B;

    size_t accBytes = (size_t)KMAX * 64 * ((D + 63) / 64) * sizeof(float);
    size_t shmem = accBytes + (size_t)S * sizeof(int);   // sseq only touched on general path
    wave_kernel<<<B, NT, shmem>>>(seqs, emb, kptr, out, S, D);
}

// round 8
// speedup vs baseline: 1.0241x; 1.0241x over previous
#include <cuda_runtime.h>
#include <cuda_bf16.h>

#define KMAX 8
#define NT 256
#define NWARP (NT / 32)
#define FULLM 0xffffffffu
#define BMAX 1024
#define DMAX 256

// Zero-initialized persistent state (reset by the kernel itself each launch).
__device__ float g_scratch[BMAX * DMAX];   // per-batch accumulators
__device__ int   g_cnt[BMAX];              // arrival counters

// ============================ FAST PATH =====================================
// grid = (KMAX, B); one CTA per (j, b). Requires S == NT*8, D even.
// out[b,d] = sum_j (1/(c_j*k)) * sum_{t: seqs[b,t]==aval_j, t<L, t+j+1<L} emb[b,t+j+1,d]
__global__ __launch_bounds__(NT)
void wave_split_kernel(const int* __restrict__ seqs,
                       const float* __restrict__ emb,
                       const int* __restrict__ kptr,
                       float* __restrict__ out,
                       int S, int D) {
    const int j    = blockIdx.x;
    const int b    = blockIdx.y;
    const int tid  = threadIdx.x;
    const int lane = tid & 31;
    const int warp = tid >> 5;

    __shared__ int warpMin[NWARP];
    __shared__ int scnt;
    __shared__ int sLast;

    int k = *kptr;
    if (k > KMAX) k = KMAX;
    if (k < 1) k = 1;

    float* scr = g_scratch + (size_t)b * D;

    if (j < k) {
        if (tid == 0) scnt = 0;

        // ---- load 8 ints/thread, boundary detect ----
        const int* seq = seqs + (size_t)b * S;
        const int base = tid << 3;
        int4 a0 = ((const int4*)(seq + base))[0];
        int4 a1 = ((const int4*)(seq + base))[1];
        int vv[8];
        vv[0]=a0.x; vv[1]=a0.y; vv[2]=a0.z; vv[3]=a0.w;
        vv[4]=a1.x; vv[5]=a1.y; vv[6]=a1.z; vv[7]=a1.w;

        int nxt = __shfl_down_sync(FULLM, vv[0], 1);
        if (lane == 31) nxt = (base + 8 < S) ? __ldg(seq + base + 8) : 0;

        int cand = S;
        if (base == 0 && vv[0] == 0) cand = 0;
        #pragma unroll
        for (int i = 0; i < 7; i++)
            if (vv[i] != 0 && vv[i + 1] == 0) cand = base + i + 1;
        if (vv[7] != 0 && nxt == 0) cand = base + 8;

        #pragma unroll
        for (int o = 16; o; o >>= 1) {
            int other = __shfl_down_sync(FULLM, cand, o);
            cand = other < cand ? other : cand;
        }
        if (lane == 0) warpMin[warp] = cand;
        __syncthreads();                                       // bar 1

        int L = warpMin[0];
        #pragma unroll
        for (int w = 1; w < NWARP; w++) { int m = warpMin[w]; L = m < L ? m : L; }

        // ---- anchor: one broadcast load (L1-hot: this CTA just read the row) ----
        int a = L - 1 - j;
        const int av = __ldg(seq + (a > 0 ? a : 0));

        // ---- match mask + CTA-wide count ----
        unsigned mymask = 0;
        #pragma unroll
        for (int i = 0; i < 8; i++)
            if (vv[i] == av && vv[i] != 0) mymask |= (1u << i);

        int wcnt = __reduce_add_sync(FULLM, __popc(mymask));
        if (lane == 0 && wcnt) atomicAdd(&scnt, wcnt);
        __syncthreads();                                       // bar 2

        const int c = scnt;
        if (c > 0) {
            const float scale = 1.0f / ((float)c * (float)k);
            const float* eb = emb + (size_t)b * S * D;

            // ---- warp-cooperative gather of matched rows (rare) ----
            unsigned tmask = __ballot_sync(FULLM, mymask != 0);
            while (tmask) {
                const int src = __ffs(tmask) - 1;
                tmask &= tmask - 1;
                unsigned em = __shfl_sync(FULLM, mymask, src);
                const int sbase = (((warp << 5) + src) << 3) + j + 1;
                while (em) {
                    const int i = __ffs(em) - 1;
                    em &= em - 1;
                    const int s = sbase + i;
                    if (s < L) {
                        const float* row = eb + (size_t)s * D;
                        for (int d = 2 * lane; d < D; d += 64) {
                            float2 e2 = *(const float2*)(row + d);
                            atomicAdd(&scr[d],     e2.x * scale);
                            atomicAdd(&scr[d + 1], e2.y * scale);
                        }
                    }
                }
            }
        }
    }

    // ---- completion: last CTA of this b copies scratch -> out, resets state ----
    __threadfence();
    __syncthreads();                                           // bar 3
    if (tid == 0) {
        int old = atomicAdd(&g_cnt[b], 1);
        sLast = (old == KMAX - 1);
    }
    __syncthreads();                                           // bar 4
    if (sLast) {
        __threadfence();
        for (int d = tid; d < D; d += NT) {
            float v = __ldcg(&scr[d]);
            out[(size_t)b * D + d] = v;
            __stcg(&scr[d], 0.0f);
        }
        if (tid == 0) atomicExch(&g_cnt[b], 0);
    }
}

// ============================ FALLBACK (R6) =================================
__global__ __launch_bounds__(NT)
void wave_fallback_kernel(const int* __restrict__ seqs,
                          const float* __restrict__ emb,
                          const int* __restrict__ kptr,
                          float* __restrict__ out,
                          int S, int D) {
    const int b    = blockIdx.x;
    const int tid  = threadIdx.x;
    const int lane = tid & 31;
    const int warp = tid >> 5;

    extern __shared__ int smem[];
    float* acc  = (float*)smem;                 // KMAX*D
    int*   sseq = smem + KMAX * D;              // S ints

    __shared__ int cnt[KMAX];
    __shared__ int sLsh;

    const int* seq = seqs + (size_t)b * S;
    int k = *kptr;
    if (k > KMAX) k = KMAX;
    if (k < 1) k = 1;

    if (tid == 0) sLsh = S;
    if (tid < KMAX) cnt[tid] = 0;
    for (int i = tid; i < KMAX * D; i += NT) acc[i] = 0.0f;
    for (int i = tid; i < S; i += NT) sseq[i] = seq[i];
    __syncthreads();
    for (int i = tid; i < S; i += NT) {
        int v = sseq[i];
        if (i == 0 && v == 0) atomicMin(&sLsh, 0);
        if (v != 0 && (i + 1 == S || sseq[i + 1] == 0)) atomicMin(&sLsh, i + 1);
    }
    __syncthreads();
    const int L = sLsh;
    int my_aval = 0;
    if (lane < k) {
        int a = L - 1 - lane;
        my_aval = sseq[a > 0 ? a : 0];
    }
    const float* eb = emb + (size_t)b * S * D;
    for (int t0 = warp * 32; t0 < L; t0 += NT) {
        const int t = t0 + lane;
        const int v = (t < L) ? sseq[t] : 0;
        for (int j = 0; j < k; j++) {
            const int av = __shfl_sync(FULLM, my_aval, j);
            unsigned m = __ballot_sync(FULLM, v == av && v != 0);
            if (!m) continue;
            if (lane == 0) atomicAdd(&cnt[j], __popc(m));
            float* aj = acc + j * D;
            while (m) {
                const int l = __ffs(m) - 1;
                m &= m - 1;
                const int s = t0 + l + j + 1;
                if (s < L) {
                    const float* row = eb + (size_t)s * D;
                    for (int d = lane; d < D; d += 32) atomicAdd(&aj[d], row[d]);
                }
            }
        }
    }
    __syncthreads();
    const float invk = 1.0f / (float)k;
    for (int d = tid; d < D; d += NT) {
        float s = 0.0f;
        for (int j = 0; j < k; j++) {
            int c = cnt[j];
            if (c > 0) s += acc[j * D + d] / (float)c;
        }
        out[(size_t)b * D + d] = s * invk;
    }
}

extern "C" void kernel_launch(void* const* d_in, const int* in_sizes, int n_in,
                              void* d_out, int out_size) {
    const int*   seqs = (const int*)d_in[0];
    const float* emb  = (const float*)d_in[1];
    const int*   kptr = (const int*)d_in[2];
    float*       out  = (float*)d_out;

    const int n_seq = in_sizes[0];   // B*S
    const int n_emb = in_sizes[1];   // B*S*D
    const int D = n_emb / n_seq;
    const int B = out_size / D;
    const int S = n_seq / B;

    if (S == NT * 8 && (D & 1) == 0 && B <= BMAX && D <= DMAX) {
        dim3 grid(KMAX, B);
        wave_split_kernel<<<grid, NT>>>(seqs, emb, kptr, out, S, D);
    } else {
        size_t shmem = (size_t)KMAX * D * sizeof(float) + (size_t)S * sizeof(int);
        wave_fallback_kernel<<<B, NT, shmem>>>(seqs, emb, kptr, out, S, D);
    }
}

// round 9
// speedup vs baseline: 1.5625x; 1.5257x over previous
#include <cuda_runtime.h>
#include <cuda_bf16.h>

#define KMAX 8
#define NT 512
#define NWARP (NT / 32)
#define FULLM 0xffffffffu

// out[b,d] = sum_j (1/(c_j*k)) * sum_{t: seqs[b,t]==aval_j, t<L, t+j+1<L} emb[b,t+j+1,d]
//   L      = nonzero prefix length of seqs[b,:] (right-padded, valid ids >= 1)
//   aval_j = seqs[b, max(L-1-j, 0)]
//   c_j    = # of t in [0,L) with seqs[b,t]==aval_j
// FAST PATH: requires S == 4*NT. One CTA per batch row. Results go straight to
// out via no-return global atomics; out is zeroed by this CTA first (ordered
// by __syncthreads).
__global__ __launch_bounds__(NT)
void wave_fast_kernel(const int* __restrict__ seqs,
                      const float* __restrict__ emb,
                      const int* __restrict__ kptr,
                      float* __restrict__ out,
                      int S, int D) {
    const int b    = blockIdx.x;
    const int tid  = threadIdx.x;
    const int lane = tid & 31;
    const int warp = tid >> 5;

    __shared__ int warpMin[NWARP];
    __shared__ int cnt[KMAX];

    int k = *kptr;
    if (k > KMAX) k = KMAX;
    if (k < 1) k = 1;

    float* ob = out + (size_t)b * D;
    for (int d = tid; d < D; d += NT) ob[d] = 0.0f;     // init output (poisoned)
    if (tid < KMAX) cnt[tid] = 0;

    // ---- load 4 ints/thread (one LDG.128), boundary detect ----
    const int* seq = seqs + (size_t)b * S;
    const int base = tid << 2;
    int4 a0 = ((const int4*)(seq + base))[0];
    int vv[4];
    vv[0] = a0.x; vv[1] = a0.y; vv[2] = a0.z; vv[3] = a0.w;

    int nxt = __shfl_down_sync(FULLM, vv[0], 1);
    if (lane == 31) nxt = (base + 4 < S) ? __ldg(seq + base + 4) : 0;

    int cand = S;
    if (base == 0 && vv[0] == 0) cand = 0;
    #pragma unroll
    for (int i = 0; i < 3; i++)
        if (vv[i] != 0 && vv[i + 1] == 0) cand = base + i + 1;
    if (vv[3] != 0 && nxt == 0) cand = base + 4;

    #pragma unroll
    for (int o = 16; o; o >>= 1) {
        int other = __shfl_down_sync(FULLM, cand, o);
        cand = other < cand ? other : cand;
    }
    if (lane == 0) warpMin[warp] = cand;
    __syncthreads();                                    // BAR 1 (also orders ob zeroing)

    int L = warpMin[0];
    #pragma unroll
    for (int w = 1; w < NWARP; w++) { int m = warpMin[w]; L = m < L ? m : L; }

    // ---- anchors: per-warp redundant fetch (L1-hot), shfl broadcast ----
    int my_aval = 0;
    if (lane < k) {
        int a = L - 1 - lane;
        my_aval = __ldg(seq + (a > 0 ? a : 0));
    }

    // ---- count pass (ALU only) ----
    #pragma unroll
    for (int j = 0; j < KMAX; j++) {
        if (j >= k) break;
        const int av = __shfl_sync(FULLM, my_aval, j);
        int c = 0;
        #pragma unroll
        for (int i = 0; i < 4; i++) c += (vv[i] == av && vv[i] != 0);
        int wcnt = __reduce_add_sync(FULLM, c);
        if (lane == 0 && wcnt) atomicAdd(&cnt[j], wcnt);
    }
    __syncthreads();                                    // BAR 2

    // ---- gather pass: scaled, fire-and-forget global atomics ----
    const float* eb = emb + (size_t)b * S * D;
    const float fk = (float)k;
    const bool deven = (D & 1) == 0;
    #pragma unroll
    for (int j = 0; j < KMAX; j++) {
        if (j >= k) break;
        const int av = __shfl_sync(FULLM, my_aval, j);
        unsigned mymask = 0;
        #pragma unroll
        for (int i = 0; i < 4; i++)
            if (vv[i] == av && vv[i] != 0) mymask |= (1u << i);
        unsigned tmask = __ballot_sync(FULLM, mymask != 0);
        if (!tmask) continue;
        const float scale = __fdividef(1.0f, (float)cnt[j] * fk);
        while (tmask) {
            const int src = __ffs(tmask) - 1;
            tmask &= tmask - 1;
            unsigned em = __shfl_sync(FULLM, mymask, src);
            const int sbase = (((warp << 5) + src) << 2) + j + 1;
            while (em) {
                const int i = __ffs(em) - 1;
                em &= em - 1;
                const int s = sbase + i;
                if (s < L) {
                    const float* row = eb + (size_t)s * D;
                    if (deven) {
                        for (int d = 2 * lane; d < D; d += 64) {
                            float2 e2 = *(const float2*)(row + d);
                            atomicAdd(&ob[d],     e2.x * scale);
                            atomicAdd(&ob[d + 1], e2.y * scale);
                        }
                    } else {
                        for (int d = lane; d < D; d += 32)
                            atomicAdd(&ob[d], row[d] * scale);
                    }
                }
            }
        }
    }
    // no epilogue, no final barrier — REDG atomics complete before kernel end
}

// ============================ FALLBACK (R6, any S) ==========================
__global__ __launch_bounds__(256)
void wave_fallback_kernel(const int* __restrict__ seqs,
                          const float* __restrict__ emb,
                          const int* __restrict__ kptr,
                          float* __restrict__ out,
                          int S, int D) {
    const int b    = blockIdx.x;
    const int tid  = threadIdx.x;
    const int lane = tid & 31;
    const int warp = tid >> 5;

    extern __shared__ int smem[];
    float* acc  = (float*)smem;                 // KMAX*D
    int*   sseq = smem + KMAX * D;              // S ints

    __shared__ int cnt[KMAX];
    __shared__ int sLsh;

    const int* seq = seqs + (size_t)b * S;
    int k = *kptr;
    if (k > KMAX) k = KMAX;
    if (k < 1) k = 1;

    if (tid == 0) sLsh = S;
    if (tid < KMAX) cnt[tid] = 0;
    for (int i = tid; i < KMAX * D; i += 256) acc[i] = 0.0f;
    for (int i = tid; i < S; i += 256) sseq[i] = seq[i];
    __syncthreads();
    for (int i = tid; i < S; i += 256) {
        int v = sseq[i];
        if (i == 0 && v == 0) atomicMin(&sLsh, 0);
        if (v != 0 && (i + 1 == S || sseq[i + 1] == 0)) atomicMin(&sLsh, i + 1);
    }
    __syncthreads();
    const int L = sLsh;
    int my_aval = 0;
    if (lane < k) {
        int a = L - 1 - lane;
        my_aval = sseq[a > 0 ? a : 0];
    }
    const float* eb = emb + (size_t)b * S * D;
    for (int t0 = warp * 32; t0 < L; t0 += 256) {
        const int t = t0 + lane;
        const int v = (t < L) ? sseq[t] : 0;
        for (int j = 0; j < k; j++) {
            const int av = __shfl_sync(FULLM, my_aval, j);
            unsigned m = __ballot_sync(FULLM, v == av && v != 0);
            if (!m) continue;
            if (lane == 0) atomicAdd(&cnt[j], __popc(m));
            float* aj = acc + j * D;
            while (m) {
                const int l = __ffs(m) - 1;
                m &= m - 1;
                const int s = t0 + l + j + 1;
                if (s < L) {
                    const float* row = eb + (size_t)s * D;
                    for (int d = lane; d < D; d += 32) atomicAdd(&aj[d], row[d]);
                }
            }
        }
    }
    __syncthreads();
    const float invk = 1.0f / (float)k;
    for (int d = tid; d < D; d += 256) {
        float s = 0.0f;
        for (int j = 0; j < k; j++) {
            int c = cnt[j];
            if (c > 0) s += acc[j * D + d] / (float)c;
        }
        out[(size_t)b * D + d] = s * invk;
    }
}

extern "C" void kernel_launch(void* const* d_in, const int* in_sizes, int n_in,
                              void* d_out, int out_size) {
    const int*   seqs = (const int*)d_in[0];
    const float* emb  = (const float*)d_in[1];
    const int*   kptr = (const int*)d_in[2];
    float*       out  = (float*)d_out;

    const int n_seq = in_sizes[0];   // B*S
    const int n_emb = in_sizes[1];   // B*S*D
    const int D = n_emb / n_seq;
    const int B = out_size / D;
    const int S = n_seq / B;

    if (S == NT * 4) {
        wave_fast_kernel<<<B, NT>>>(seqs, emb, kptr, out, S, D);
    } else {
        size_t shmem = (size_t)KMAX * D * sizeof(float) + (size_t)S * sizeof(int);
        wave_fallback_kernel<<<B, 256, shmem>>>(seqs, emb, kptr, out, S, D);
    }
}

// round 10
// speedup vs baseline: 1.8240x; 1.1674x over previous
#include <cuda_runtime.h>
#include <cuda_bf16.h>

#define KMAX 8
#define NT 512
#define NWARP (NT / 32)
#define FULLM 0xffffffffu

// out[b,d] = sum_j (1/(c_j*k)) * sum_{t: seqs[b,t]==aval_j, t<L, t+j+1<L} emb[b,t+j+1,d]
//   L      = nonzero prefix length of seqs[b,:] (right-padded, valid ids >= 1)
//   aval_j = seqs[b, max(L-1-j, 0)]
//   c_j    = # of t in [0,L) with seqs[b,t]==aval_j
// FAST PATH: requires S == 4*NT. One CTA per batch row; results fired straight
// into out via no-return global atomics (out zeroed by this CTA, ordered by bar 1).
__global__ __launch_bounds__(NT)
void wave_fast_kernel(const int* __restrict__ seqs,
                      const float* __restrict__ emb,
                      const int* __restrict__ kptr,
                      float* __restrict__ out,
                      int S, int D) {
    const int b    = blockIdx.x;
    const int tid  = threadIdx.x;
    const int lane = tid & 31;
    const int warp = tid >> 5;

    __shared__ int warpMin[NWARP];
    __shared__ int cnt[KMAX];

    int k = *kptr;
    if (k > KMAX) k = KMAX;
    if (k < 1) k = 1;

    float* ob = out + (size_t)b * D;
    for (int d = tid; d < D; d += NT) ob[d] = 0.0f;     // init output (poisoned)
    if (tid < KMAX) cnt[tid] = 0;

    // ---- load 4 ints/thread (one LDG.128), boundary detect ----
    const int* seq = seqs + (size_t)b * S;
    const int base = tid << 2;
    int4 a0 = ((const int4*)(seq + base))[0];
    int vv[4];
    vv[0] = a0.x; vv[1] = a0.y; vv[2] = a0.z; vv[3] = a0.w;

    int nxt = __shfl_down_sync(FULLM, vv[0], 1);
    if (lane == 31) nxt = (base + 4 < S) ? __ldg(seq + base + 4) : 0;

    int cand = S;
    if (base == 0 && vv[0] == 0) cand = 0;
    #pragma unroll
    for (int i = 0; i < 3; i++)
        if (vv[i] != 0 && vv[i + 1] == 0) cand = base + i + 1;
    if (vv[3] != 0 && nxt == 0) cand = base + 4;

    #pragma unroll
    for (int o = 16; o; o >>= 1) {
        int other = __shfl_down_sync(FULLM, cand, o);
        cand = other < cand ? other : cand;
    }
    if (lane == 0) warpMin[warp] = cand;
    __syncthreads();                                    // BAR 1 (orders ob zeroing too)

    int L = warpMin[0];
    #pragma unroll
    for (int w = 1; w < NWARP; w++) { int m = warpMin[w]; L = m < L ? m : L; }

    // ---- anchors: per-warp redundant fetch (L1-hot), broadcast to registers ----
    int my_aval = 0;
    if (lane < k) {
        int a = L - 1 - lane;
        my_aval = __ldg(seq + (a > 0 ? a : 0));
    }
    int av[KMAX];
    #pragma unroll
    for (int j = 0; j < KMAX; j++) av[j] = __shfl_sync(FULLM, my_aval, j);

    // ---- single mask pass (cached) + count reduce ----
    unsigned mk[KMAX];
    #pragma unroll
    for (int j = 0; j < KMAX; j++) {
        mk[j] = 0;
        if (j < k) {
            #pragma unroll
            for (int i = 0; i < 4; i++)
                if (vv[i] == av[j] && vv[i] != 0) mk[j] |= (1u << i);
            int wcnt = __reduce_add_sync(FULLM, __popc(mk[j]));
            if (lane == 0 && wcnt) atomicAdd(&cnt[j], wcnt);
        }
    }
    __syncthreads();                                    // BAR 2

    // ---- gather pass: scaled, fire-and-forget global atomics ----
    const float* eb = emb + (size_t)b * S * D;
    const float fk = (float)k;
    #pragma unroll
    for (int j = 0; j < KMAX; j++) {
        if (j >= k) break;
        unsigned tmask = __ballot_sync(FULLM, mk[j] != 0);
        if (!tmask) continue;
        const float scale = __fdividef(1.0f, (float)cnt[j] * fk);
        while (tmask) {
            const int src = __ffs(tmask) - 1;
            tmask &= tmask - 1;
            unsigned em = __shfl_sync(FULLM, mk[j], src);
            const int sbase = (((warp << 5) + src) << 2) + j + 1;
            while (em) {
                const int i = __ffs(em) - 1;
                em &= em - 1;
                const int s = sbase + i;
                if (s < L) {
                    const float* row = eb + (size_t)s * D;
                    if (D == 64) {                      // bench shape: fully unrolled
                        float2 e2 = *(const float2*)(row + 2 * lane);
                        atomicAdd(&ob[2 * lane],     e2.x * scale);
                        atomicAdd(&ob[2 * lane + 1], e2.y * scale);
                    } else if ((D & 1) == 0) {
                        for (int d = 2 * lane; d < D; d += 64) {
                            float2 e2 = *(const float2*)(row + d);
                            atomicAdd(&ob[d],     e2.x * scale);
                            atomicAdd(&ob[d + 1], e2.y * scale);
                        }
                    } else {
                        for (int d = lane; d < D; d += 32)
                            atomicAdd(&ob[d], row[d] * scale);
                    }
                }
            }
        }
    }
    // no epilogue, no final barrier — REDG atomics drain before kernel completion
}

// ============================ FALLBACK (R6, any S) ==========================
__global__ __launch_bounds__(256)
void wave_fallback_kernel(const int* __restrict__ seqs,
                          const float* __restrict__ emb,
                          const int* __restrict__ kptr,
                          float* __restrict__ out,
                          int S, int D) {
    const int b    = blockIdx.x;
    const int tid  = threadIdx.x;
    const int lane = tid & 31;
    const int warp = tid >> 5;

    extern __shared__ int smem[];
    float* acc  = (float*)smem;                 // KMAX*D
    int*   sseq = smem + KMAX * D;              // S ints

    __shared__ int cnt[KMAX];
    __shared__ int sLsh;

    const int* seq = seqs + (size_t)b * S;
    int k = *kptr;
    if (k > KMAX) k = KMAX;
    if (k < 1) k = 1;

    if (tid == 0) sLsh = S;
    if (tid < KMAX) cnt[tid] = 0;
    for (int i = tid; i < KMAX * D; i += 256) acc[i] = 0.0f;
    for (int i = tid; i < S; i += 256) sseq[i] = seq[i];
    __syncthreads();
    for (int i = tid; i < S; i += 256) {
        int v = sseq[i];
        if (i == 0 && v == 0) atomicMin(&sLsh, 0);
        if (v != 0 && (i + 1 == S || sseq[i + 1] == 0)) atomicMin(&sLsh, i + 1);
    }
    __syncthreads();
    const int L = sLsh;
    int my_aval = 0;
    if (lane < k) {
        int a = L - 1 - lane;
        my_aval = sseq[a > 0 ? a : 0];
    }
    const float* eb = emb + (size_t)b * S * D;
    for (int t0 = warp * 32; t0 < L; t0 += 256) {
        const int t = t0 + lane;
        const int v = (t < L) ? sseq[t] : 0;
        for (int j = 0; j < k; j++) {
            const int av = __shfl_sync(FULLM, my_aval, j);
            unsigned m = __ballot_sync(FULLM, v == av && v != 0);
            if (!m) continue;
            if (lane == 0) atomicAdd(&cnt[j], __popc(m));
            float* aj = acc + j * D;
            while (m) {
                const int l = __ffs(m) - 1;
                m &= m - 1;
                const int s = t0 + l + j + 1;
                if (s < L) {
                    const float* row = eb + (size_t)s * D;
                    for (int d = lane; d < D; d += 32) atomicAdd(&aj[d], row[d]);
                }
            }
        }
    }
    __syncthreads();
    const float invk = 1.0f / (float)k;
    for (int d = tid; d < D; d += 256) {
        float s = 0.0f;
        for (int j = 0; j < k; j++) {
            int c = cnt[j];
            if (c > 0) s += acc[j * D + d] / (float)c;
        }
        out[(size_t)b * D + d] = s * invk;
    }
}

extern "C" void kernel_launch(void* const* d_in, const int* in_sizes, int n_in,
                              void* d_out, int out_size) {
    const int*   seqs = (const int*)d_in[0];
    const float* emb  = (const float*)d_in[1];
    const int*   kptr = (const int*)d_in[2];
    float*       out  = (float*)d_out;

    const int n_seq = in_sizes[0];   // B*S
    const int n_emb = in_sizes[1];   // B*S*D
    const int D = n_emb / n_seq;
    const int B = out_size / D;
    const int S = n_seq / B;

    if (S == NT * 4) {
        wave_fast_kernel<<<B, NT>>>(seqs, emb, kptr, out, S, D);
    } else {
        size_t shmem = (size_t)KMAX * D * sizeof(float) + (size_t)S * sizeof(int);
        wave_fallback_kernel<<<B, 256, shmem>>>(seqs, emb, kptr, out, S, D);
    }
}